// round 3
// baseline (speedup 1.0000x reference)
#include <cuda_runtime.h>
#include <cuda_bf16.h>

#define NN 100000
#define NE 3200000
#define NG 128

// ---- scratch (zero-init device globals; 16B-aligned for vector ld/st/red) ----
__device__ __align__(16) int   g_deg[NN];
__device__ __align__(16) float g_dinv[NN];
__device__ __align__(16) float g_agg1[NN * 4];    // 3 ch padded to 4 for red.v4
__device__ __align__(16) float g_h1[NN * 32];
__device__ __align__(16) float g_agg2[NN * 32];
__device__ __align__(16) float g_g3[NN * 2];
__device__ __align__(16) float g_agg3[NN * 2];
__device__ __align__(16) float g_psum[NG * 2];
__device__ __align__(16) int   g_pcnt[NG];

__device__ __forceinline__ void red4(float* p, float a, float b, float c, float d) {
    asm volatile("red.global.add.v4.f32 [%0], {%1,%2,%3,%4};"
                 :: "l"(p), "f"(a), "f"(b), "f"(c), "f"(d) : "memory");
}
__device__ __forceinline__ void red2(float* p, float a, float b) {
    asm volatile("red.global.add.v2.f32 [%0], {%1,%2};"
                 :: "l"(p), "f"(a), "f"(b) : "memory");
}

// ---- 1: reset per-call state ----
__global__ void k_init() {
    int i = blockIdx.x * blockDim.x + threadIdx.x;
    if (i < NN) g_deg[i] = 1;            // self-loop
    if (i < NG * 2) g_psum[i] = 0.f;
    if (i < NG) g_pcnt[i] = 0;
}

// ---- 2: in-degree from int32 dst indices ----
__global__ void k_edge_prep(const int* __restrict__ ei) {
    int e = blockIdx.x * blockDim.x + threadIdx.x;
    if (e >= NE) return;
    atomicAdd(&g_deg[ei[NE + e]], 1);
}

// ---- 3: dinv + layer-1 self-loop init (agg1 = dinv^2 * x) ----
__global__ void k_node_prep(const float* __restrict__ x) {
    int i = blockIdx.x * blockDim.x + threadIdx.x;
    if (i >= NN) return;
    float di = rsqrtf((float)g_deg[i]);  // deg >= 1 always
    g_dinv[i] = di;
    float w = di * di;
    float x0 = x[i * 3 + 0], x1 = x[i * 3 + 1], x2 = x[i * 3 + 2];
    *(float4*)(g_agg1 + i * 4) = make_float4(w * x0, w * x1, w * x2, 0.f);
}

// ---- 4: layer-1 edge scatter (3 channels) ----
__global__ void k_edge1(const int* __restrict__ ei, const float* __restrict__ x) {
    int e = blockIdx.x * blockDim.x + threadIdx.x;
    if (e >= NE) return;
    int s = ei[e], d = ei[NE + e];
    float w = g_dinv[s] * g_dinv[d];
    float x0 = __ldg(x + s * 3 + 0);
    float x1 = __ldg(x + s * 3 + 1);
    float x2 = __ldg(x + s * 3 + 2);
    red4(g_agg1 + d * 4, w * x0, w * x1, w * x2, 0.f);
}

// ---- 5: h1 = relu(agg1 @ W1 + b1); agg2 init = dinv^2 * h1 ----
__global__ void k_node1(const float* __restrict__ W1, const float* __restrict__ b1) {
    __shared__ float sW[96];
    __shared__ float sb[32];
    int t = threadIdx.x;
    if (t < 96) sW[t] = W1[t];
    if (t < 32) sb[t] = b1[t];
    __syncthreads();
    int i = blockIdx.x * blockDim.x + t;
    if (i >= NN) return;
    float4 a = *(const float4*)(g_agg1 + i * 4);
    float di = g_dinv[i];
    float w = di * di;
    float out[32];
#pragma unroll
    for (int j = 0; j < 32; j++) {
        float h = sb[j] + a.x * sW[j] + a.y * sW[32 + j] + a.z * sW[64 + j];
        out[j] = fmaxf(h, 0.f);
    }
    float4* ph = (float4*)(g_h1 + i * 32);
    float4* pa = (float4*)(g_agg2 + i * 32);
#pragma unroll
    for (int k = 0; k < 8; k++) {
        float4 v = make_float4(out[4 * k], out[4 * k + 1], out[4 * k + 2], out[4 * k + 3]);
        ph[k] = v;
        pa[k] = make_float4(w * v.x, w * v.y, w * v.z, w * v.w);
    }
}

// ---- 6: layer-2 edge scatter (32 channels) — the dominant kernel ----
__global__ void k_edge2(const int* __restrict__ ei) {
    int e = blockIdx.x * blockDim.x + threadIdx.x;
    if (e >= NE) return;
    int s = ei[e], d = ei[NE + e];
    float w = g_dinv[s] * g_dinv[d];
    const float4* hs = (const float4*)(g_h1 + s * 32);
    float* ad = g_agg2 + d * 32;
#pragma unroll
    for (int k = 0; k < 8; k++) {
        float4 v = __ldg(hs + k);
        red4(ad + 4 * k, w * v.x, w * v.y, w * v.z, w * v.w);
    }
}

// ---- 7: h2 = relu(agg2 @ W2 + b2) (regs only); g3 = h2 @ W3; agg3 init ----
__global__ void k_node2(const float* __restrict__ W2, const float* __restrict__ b2,
                        const float* __restrict__ W3) {
    __shared__ float sW2[2048];
    __shared__ float sb2[64];
    __shared__ float sW3[128];
    int t = threadIdx.x;
    for (int k = t; k < 2048; k += blockDim.x) sW2[k] = W2[k];
    if (t < 64) sb2[t] = b2[t];
    if (t < 128) sW3[t] = W3[t];
    __syncthreads();
    int i = blockIdx.x * blockDim.x + t;
    if (i >= NN) return;
    float a[32];
    const float4* pa = (const float4*)(g_agg2 + i * 32);
#pragma unroll
    for (int k = 0; k < 8; k++) {
        float4 v = pa[k];
        a[4 * k] = v.x; a[4 * k + 1] = v.y; a[4 * k + 2] = v.z; a[4 * k + 3] = v.w;
    }
    float g0 = 0.f, g1 = 0.f;
#pragma unroll 4
    for (int j = 0; j < 64; j++) {
        float acc = sb2[j];
#pragma unroll
        for (int c = 0; c < 32; c++) acc += a[c] * sW2[c * 64 + j];
        float h = fmaxf(acc, 0.f);
        g0 += h * sW3[j * 2];
        g1 += h * sW3[j * 2 + 1];
    }
    float di = g_dinv[i];
    float w = di * di;
    *(float2*)(g_g3 + i * 2) = make_float2(g0, g1);
    *(float2*)(g_agg3 + i * 2) = make_float2(w * g0, w * g1);
}

// ---- 8: layer-3 edge scatter (2 channels) ----
__global__ void k_edge3(const int* __restrict__ ei) {
    int e = blockIdx.x * blockDim.x + threadIdx.x;
    if (e >= NE) return;
    int s = ei[e], d = ei[NE + e];
    float w = g_dinv[s] * g_dinv[d];
    float2 v = *(const float2*)(g_g3 + s * 2);
    red2(g_agg3 + d * 2, w * v.x, w * v.y);
}

// ---- 9: pooling via shared bins ----
__global__ void k_pool(const int* __restrict__ batch) {
    __shared__ float ss[NG * 2];
    __shared__ int   sc[NG];
    int t = threadIdx.x;
    for (int k = t; k < NG * 2; k += blockDim.x) ss[k] = 0.f;
    for (int k = t; k < NG; k += blockDim.x) sc[k] = 0;
    __syncthreads();
    for (int i = blockIdx.x * blockDim.x + t; i < NN; i += gridDim.x * blockDim.x) {
        int b = batch[i];
        float2 v = *(const float2*)(g_agg3 + i * 2);
        atomicAdd(&ss[b * 2], v.x);
        atomicAdd(&ss[b * 2 + 1], v.y);
        atomicAdd(&sc[b], 1);
    }
    __syncthreads();
    for (int k = t; k < NG * 2; k += blockDim.x) atomicAdd(&g_psum[k], ss[k]);
    for (int k = t; k < NG; k += blockDim.x) atomicAdd(&g_pcnt[k], sc[k]);
}

// ---- 10: out = psum / cnt + b3 ----
__global__ void k_final(float* __restrict__ out, const float* __restrict__ b3) {
    int t = threadIdx.x;
    if (t >= NG * 2) return;
    int g = t >> 1, c = t & 1;
    float cnt = (float)g_pcnt[g];
    out[t] = g_psum[t] / fmaxf(cnt, 1.f) + b3[c];
}

extern "C" void kernel_launch(void* const* d_in, const int* in_sizes, int n_in,
                              void* d_out, int out_size) {
    // Resolve inputs BY ELEMENT COUNT (all nine are distinct) — immune to
    // any metadata ordering mismatch. edge_index/batch are int32 (JAX
    // default x64-disabled semantics; harness only carries f32/i32/bf16).
    const float* x     = nullptr;   // 300000
    const int*   ei    = nullptr;   // 6400000 (int32!)
    const int*   batch = nullptr;   // 100000  (int32!)
    const float* W1    = nullptr;   // 96
    const float* b1    = nullptr;   // 32
    const float* W2    = nullptr;   // 2048
    const float* b2    = nullptr;   // 64
    const float* W3    = nullptr;   // 128
    const float* b3    = nullptr;   // 2
    for (int i = 0; i < n_in; i++) {
        switch (in_sizes[i]) {
            case 300000:  x     = (const float*)d_in[i]; break;
            case 6400000: ei    = (const int*)d_in[i];   break;
            case 100000:  batch = (const int*)d_in[i];   break;
            case 96:      W1    = (const float*)d_in[i]; break;
            case 32:      b1    = (const float*)d_in[i]; break;
            case 2048:    W2    = (const float*)d_in[i]; break;
            case 64:      b2    = (const float*)d_in[i]; break;
            case 128:     W3    = (const float*)d_in[i]; break;
            case 2:       b3    = (const float*)d_in[i]; break;
        }
    }
    float* out = (float*)d_out;

    const int TB = 256;
    const int nodeBlocks = (NN + TB - 1) / TB;
    const int edgeBlocks = (NE + TB - 1) / TB;

    k_init<<<nodeBlocks, TB>>>();
    k_edge_prep<<<edgeBlocks, TB>>>(ei);
    k_node_prep<<<nodeBlocks, TB>>>(x);
    k_edge1<<<edgeBlocks, TB>>>(ei, x);
    k_node1<<<nodeBlocks, TB>>>(W1, b1);
    k_edge2<<<edgeBlocks, TB>>>(ei);
    k_node2<<<nodeBlocks, TB>>>(W2, b2, W3);
    k_edge3<<<edgeBlocks, TB>>>(ei);
    k_pool<<<128, TB>>>(batch);
    k_final<<<1, 256>>>(out, b3);
}

// round 4
// speedup vs baseline: 1.8857x; 1.8857x over previous
#include <cuda_runtime.h>
#include <cuda_bf16.h>

#define NN 100000
#define NE 3200000
#define NG 128
#define NB_SCAN 391   // ceil(NN/256)

// ---- scratch (zero-init device globals; no allocation anywhere) ----
__device__ __align__(16) int   g_deg[NN];       // real in-degree (no self-loop)
__device__ __align__(16) float g_dinv[NN];
__device__ __align__(16) int   g_loc[NN];       // block-local exclusive scan
__device__ __align__(16) int   g_bsum[NB_SCAN];
__device__ __align__(16) int   g_bscan[NB_SCAN];
__device__ __align__(16) int   g_off[NN];       // CSR row start
__device__ __align__(16) int   g_cur[NN];       // fill cursor
__device__ __align__(16) int2  g_csr[NE];       // {src, weight-as-int}
__device__ __align__(16) float g_agg1[NN * 4];  // 3 ch padded to 4
__device__ __align__(16) float g_h1[NN * 32];
__device__ __align__(16) float g_agg2[NN * 32];
__device__ __align__(16) float g_g3[NN * 2];
__device__ __align__(16) float g_psum[NG * 2];
__device__ __align__(16) int   g_pcnt[NG];

// ---- 1: reset per-call state ----
__global__ void k_init() {
    int i = blockIdx.x * blockDim.x + threadIdx.x;
    if (i < NN) g_deg[i] = 0;
    if (i < NG * 2) g_psum[i] = 0.f;
    if (i < NG) g_pcnt[i] = 0;
}

// ---- 2: in-degree ----
__global__ void k_deg(const int* __restrict__ ei) {
    int e = blockIdx.x * blockDim.x + threadIdx.x;
    if (e >= NE) return;
    atomicAdd(&g_deg[ei[NE + e]], 1);
}

// ---- 3a: per-block exclusive scan of deg ----
__global__ void k_scanA() {
    __shared__ int s[256];
    int t = threadIdx.x;
    int i = blockIdx.x * 256 + t;
    int d = (i < NN) ? g_deg[i] : 0;
    s[t] = d;
    __syncthreads();
#pragma unroll
    for (int o = 1; o < 256; o <<= 1) {
        int v = (t >= o) ? s[t - o] : 0;
        __syncthreads();
        s[t] += v;
        __syncthreads();
    }
    if (i < NN) g_loc[i] = s[t] - d;
    if (t == 255) g_bsum[blockIdx.x] = s[255];
}

// ---- 3b: scan of block sums (single block of 512 covers 391) ----
__global__ void k_scanB() {
    __shared__ int s[512];
    int t = threadIdx.x;
    int v = (t < NB_SCAN) ? g_bsum[t] : 0;
    s[t] = v;
    __syncthreads();
#pragma unroll
    for (int o = 1; o < 512; o <<= 1) {
        int u = (t >= o) ? s[t - o] : 0;
        __syncthreads();
        s[t] += u;
        __syncthreads();
    }
    if (t < NB_SCAN) g_bscan[t] = s[t] - v;
}

// ---- 3c: final offsets + cursor + dinv ----
__global__ void k_scanC() {
    int i = blockIdx.x * blockDim.x + threadIdx.x;
    if (i >= NN) return;
    int off = g_loc[i] + g_bscan[i >> 8];
    g_off[i] = off;
    g_cur[i] = off;
    g_dinv[i] = rsqrtf((float)(g_deg[i] + 1));   // +1 self-loop
}

// ---- 4: fill CSR with precomputed edge weight ----
__global__ void k_fill(const int* __restrict__ ei) {
    int e = blockIdx.x * blockDim.x + threadIdx.x;
    if (e >= NE) return;
    int s = ei[e], d = ei[NE + e];
    float w = g_dinv[s] * g_dinv[d];
    int pos = atomicAdd(&g_cur[d], 1);
    g_csr[pos] = make_int2(s, __float_as_int(w));
}

// ---- 5: layer-1 gather (3 channels), one thread per node ----
__global__ void k_gather1(const float* __restrict__ x) {
    int i = blockIdx.x * blockDim.x + threadIdx.x;
    if (i >= NN) return;
    float di = g_dinv[i];
    float ws = di * di;
    float a0 = ws * x[i * 3 + 0];
    float a1 = ws * x[i * 3 + 1];
    float a2 = ws * x[i * 3 + 2];
    int beg = g_off[i], end = beg + g_deg[i];
    for (int e = beg; e < end; e++) {
        int2 r = g_csr[e];
        float w = __int_as_float(r.y);
        const float* xs = x + (size_t)r.x * 3;
        a0 += w * __ldg(xs + 0);
        a1 += w * __ldg(xs + 1);
        a2 += w * __ldg(xs + 2);
    }
    *(float4*)(g_agg1 + i * 4) = make_float4(a0, a1, a2, 0.f);
}

// ---- 6: h1 = relu(agg1 @ W1 + b1) ----
__global__ void k_node1(const float* __restrict__ W1, const float* __restrict__ b1) {
    __shared__ float sW[96];
    __shared__ float sb[32];
    int t = threadIdx.x;
    if (t < 96) sW[t] = W1[t];
    if (t < 32) sb[t] = b1[t];
    __syncthreads();
    int i = blockIdx.x * blockDim.x + t;
    if (i >= NN) return;
    float4 a = *(const float4*)(g_agg1 + i * 4);
    float4* ph = (float4*)(g_h1 + i * 32);
#pragma unroll
    for (int k = 0; k < 8; k++) {
        float4 v;
        v.x = fmaxf(sb[4*k+0] + a.x * sW[4*k+0] + a.y * sW[32+4*k+0] + a.z * sW[64+4*k+0], 0.f);
        v.y = fmaxf(sb[4*k+1] + a.x * sW[4*k+1] + a.y * sW[32+4*k+1] + a.z * sW[64+4*k+1], 0.f);
        v.z = fmaxf(sb[4*k+2] + a.x * sW[4*k+2] + a.y * sW[32+4*k+2] + a.z * sW[64+4*k+2], 0.f);
        v.w = fmaxf(sb[4*k+3] + a.x * sW[4*k+3] + a.y * sW[32+4*k+3] + a.z * sW[64+4*k+3], 0.f);
        ph[k] = v;
    }
}

// ---- 7: layer-2 gather (32 channels), 8 threads per node (one float4 each) ----
__global__ void k_gather2() {
    int gid = blockIdx.x * blockDim.x + threadIdx.x;
    if (gid >= NN * 8) return;
    int i = gid >> 3;
    int c = gid & 7;
    float di = g_dinv[i];
    float ws = di * di;
    float4 self = __ldg((const float4*)(g_h1 + i * 32) + c);
    float4 acc = make_float4(ws * self.x, ws * self.y, ws * self.z, ws * self.w);
    int beg = g_off[i], end = beg + g_deg[i];
    for (int e = beg; e < end; e++) {
        int2 r = __ldg(&g_csr[e]);
        float w = __int_as_float(r.y);
        float4 v = __ldg((const float4*)(g_h1 + (size_t)r.x * 32) + c);
        acc.x += w * v.x; acc.y += w * v.y; acc.z += w * v.z; acc.w += w * v.w;
    }
    ((float4*)(g_agg2 + i * 32))[c] = acc;
}

// ---- 8: h2 = relu(agg2 @ W2 + b2) in regs; g3 = h2 @ W3 ----
__global__ void k_node2(const float* __restrict__ W2, const float* __restrict__ b2,
                        const float* __restrict__ W3) {
    __shared__ float sW2[2048];
    __shared__ float sb2[64];
    __shared__ float sW3[128];
    int t = threadIdx.x;
    for (int k = t; k < 2048; k += blockDim.x) sW2[k] = W2[k];
    if (t < 64) sb2[t] = b2[t];
    if (t < 128) sW3[t] = W3[t];
    __syncthreads();
    int i = blockIdx.x * blockDim.x + t;
    if (i >= NN) return;
    float a[32];
    const float4* pa = (const float4*)(g_agg2 + i * 32);
#pragma unroll
    for (int k = 0; k < 8; k++) {
        float4 v = pa[k];
        a[4*k] = v.x; a[4*k+1] = v.y; a[4*k+2] = v.z; a[4*k+3] = v.w;
    }
    float g0 = 0.f, g1 = 0.f;
#pragma unroll 4
    for (int j = 0; j < 64; j++) {
        float acc = sb2[j];
#pragma unroll
        for (int c = 0; c < 32; c++) acc += a[c] * sW2[c * 64 + j];
        float h = fmaxf(acc, 0.f);
        g0 += h * sW3[j * 2];
        g1 += h * sW3[j * 2 + 1];
    }
    *(float2*)(g_g3 + i * 2) = make_float2(g0, g1);
}

// ---- 9: layer-3 gather (2 ch) fused with mean-pool binning ----
__global__ void k_gather3_pool(const int* __restrict__ batch) {
    __shared__ float ss[NG * 2];
    __shared__ int   sc[NG];
    int t = threadIdx.x;
    for (int k = t; k < NG * 2; k += blockDim.x) ss[k] = 0.f;
    for (int k = t; k < NG; k += blockDim.x) sc[k] = 0;
    __syncthreads();
    for (int i = blockIdx.x * blockDim.x + t; i < NN; i += gridDim.x * blockDim.x) {
        float di = g_dinv[i];
        float ws = di * di;
        float2 self = *(const float2*)(g_g3 + i * 2);
        float a0 = ws * self.x, a1 = ws * self.y;
        int beg = g_off[i], end = beg + g_deg[i];
        for (int e = beg; e < end; e++) {
            int2 r = __ldg(&g_csr[e]);
            float w = __int_as_float(r.y);
            float2 v = *(const float2*)(g_g3 + (size_t)r.x * 2);
            a0 += w * v.x; a1 += w * v.y;
        }
        int b = batch[i];
        atomicAdd(&ss[b * 2], a0);
        atomicAdd(&ss[b * 2 + 1], a1);
        atomicAdd(&sc[b], 1);
    }
    __syncthreads();
    for (int k = t; k < NG * 2; k += blockDim.x) atomicAdd(&g_psum[k], ss[k]);
    for (int k = t; k < NG; k += blockDim.x) atomicAdd(&g_pcnt[k], sc[k]);
}

// ---- 10: out = psum / cnt + b3 ----
__global__ void k_final(float* __restrict__ out, const float* __restrict__ b3) {
    int t = threadIdx.x;
    if (t >= NG * 2) return;
    int g = t >> 1, c = t & 1;
    float cnt = (float)g_pcnt[g];
    out[t] = g_psum[t] / fmaxf(cnt, 1.f) + b3[c];
}

extern "C" void kernel_launch(void* const* d_in, const int* in_sizes, int n_in,
                              void* d_out, int out_size) {
    // Resolve inputs BY ELEMENT COUNT (all nine distinct).
    const float* x = nullptr; const int* ei = nullptr; const int* batch = nullptr;
    const float *W1 = nullptr, *b1 = nullptr, *W2 = nullptr, *b2 = nullptr,
                *W3 = nullptr, *b3 = nullptr;
    for (int i = 0; i < n_in; i++) {
        switch (in_sizes[i]) {
            case 300000:  x     = (const float*)d_in[i]; break;
            case 6400000: ei    = (const int*)d_in[i];   break;
            case 100000:  batch = (const int*)d_in[i];   break;
            case 96:      W1    = (const float*)d_in[i]; break;
            case 32:      b1    = (const float*)d_in[i]; break;
            case 2048:    W2    = (const float*)d_in[i]; break;
            case 64:      b2    = (const float*)d_in[i]; break;
            case 128:     W3    = (const float*)d_in[i]; break;
            case 2:       b3    = (const float*)d_in[i]; break;
        }
    }
    float* out = (float*)d_out;

    const int TB = 256;
    const int nodeBlocks = (NN + TB - 1) / TB;          // 391
    const int edgeBlocks = (NE + TB - 1) / TB;          // 12500
    const int g2Blocks   = (NN * 8 + TB - 1) / TB;      // 3125

    k_init<<<nodeBlocks, TB>>>();
    k_deg<<<edgeBlocks, TB>>>(ei);
    k_scanA<<<NB_SCAN, 256>>>();
    k_scanB<<<1, 512>>>();
    k_scanC<<<nodeBlocks, TB>>>();
    k_fill<<<edgeBlocks, TB>>>(ei);
    k_gather1<<<nodeBlocks, TB>>>(x);
    k_node1<<<nodeBlocks, TB>>>(W1, b1);
    k_gather2<<<g2Blocks, TB>>>();
    k_node2<<<nodeBlocks, TB>>>(W2, b2, W3);
    k_gather3_pool<<<256, TB>>>(batch);
    k_final<<<1, 256>>>(out, b3);
}